// round 14
// baseline (speedup 1.0000x reference)
#include <cuda_runtime.h>
#include <cuda_bf16.h>
#include <cuda_fp8.h>
#include <cstdint>

#define NW 10
#define DIM 1024
#define HID 64

// WPH: bf16 w_hi in HMMA k16 B-fragment layout (validated R3-R13), +8 pad tiles.
// uint4 index = tile*64 + pair*32 + lane ; u32 slot = (chunk&1)*2 + s ;
// lane = (n&7)*4 + ((c&7)>>1), s = (c>>3)&1, h = c&1.
__device__ __align__(16) unsigned short WPH[131072 + 4096];

// WQ8: e4m3 fragments for the merged correction (K=128 virtual: kk<64 -> w8[c],
// kk>=64 -> wlo_s8[c]) in m16n8k32 B layout: uint4 index = tile*64 + j2*32 + lane4,
// uint4 = {b0_{2j2}, b1_{2j2}, b0_{2j2+1}, b1_{2j2+1}};
// lane4 = (n&7)*4 + ((c>>2)&3), breg = (c>>4)&1, byte = c&3, j = (hi?0:2)+(c>>5).
__device__ __align__(16) unsigned char WQ8[(256 + 8) * 64 * 16];

// ---------------------------------------------------------------------------
// Circuit kernel (R11 reductions): fused RXRY, CNOT ring as one gather,
// RY1 dropped on qubits 0-2 (summed-out bits; output invariant).
// ---------------------------------------------------------------------------
__device__ __forceinline__ void gate1q(float2* psi, int tid, int bit,
    float g00x, float g00y, float g01x, float g01y,
    float g10x, float g10y, float g11x, float g11y)
{
    const int lowmask = bit - 1;
    const int i0 = ((tid & ~lowmask) << 1) | (tid & lowmask);
    const int i1 = i0 | bit;
    const float2 a = psi[i0], b = psi[i1];
    float2 n0, n1;
    n0.x = g00x*a.x - g00y*a.y + g01x*b.x - g01y*b.y;
    n0.y = g00x*a.y + g00y*a.x + g01x*b.y + g01y*b.x;
    n1.x = g10x*a.x - g10y*a.y + g11x*b.x - g11y*b.y;
    n1.y = g10x*a.y + g10y*a.x + g11x*b.y + g11y*b.x;
    psi[i0] = n0; psi[i1] = n1;
}

__device__ __forceinline__ unsigned char to_e4m3(float v) {
    return (unsigned char)__nv_cvt_float_to_fp8(v, __NV_SATFINITE, __NV_E4M3);
}

__global__ void qsa_circuit(const float* __restrict__ rx0,
                            const float* __restrict__ ry0,
                            const float* __restrict__ ry1)
{
    __shared__ float2 psi[DIM];
    const int tid = threadIdx.x;   // 512
    const int c = blockIdx.x;      // 0..63

    psi[tid]       = make_float2(0.f, 0.f);
    psi[tid + 512] = make_float2(0.f, 0.f);
    __syncthreads();
    if (tid == 0) psi[c] = make_float2(1.f, 0.f);
    __syncthreads();

    for (int j = 0; j < NW; j++) {
        const int bit = 1 << (NW - 1 - j);
        float s1, c1, s2, c2;
        sincosf(0.5f * rx0[j], &s1, &c1);
        sincosf(0.5f * ry0[j], &s2, &c2);
        gate1q(psi, tid, bit,
               c2*c1,  s2*s1,  -s2*c1, -c2*s1,
               s2*c1, -c2*s1,   c2*c1, -s2*s1);
        __syncthreads();
    }
    {   // CNOT ring: one permutation gather
        float2 v[2];
        #pragma unroll
        for (int rep = 0; rep < 2; rep++) {
            int src = tid + rep * 512;
            #pragma unroll
            for (int j = NW - 1; j >= 0; j--) {
                const int cbit = 1 << (NW - 1 - j);
                const int tbit = 1 << (NW - 1 - ((j + 1) % NW));
                if (src & cbit) src ^= tbit;
            }
            v[rep] = psi[src];
        }
        __syncthreads();
        psi[tid]       = v[0];
        psi[tid + 512] = v[1];
        __syncthreads();
    }
    for (int j = 3; j < NW; j++) {
        const int bit = 1 << (NW - 1 - j);
        float s, cc;
        sincosf(0.5f * ry1[j], &s, &cc);
        gate1q(psi, tid, bit, cc, 0.f, -s, 0.f, s, 0.f, cc, 0.f);
        __syncthreads();
    }

    // scatter column c: bf16 hi into WPH (k16 layout), e4m3 w / w_lo*256 into WQ8
    const int chunk = c >> 4;
    const int s16 = (c >> 3) & 1;
    const int lq  = (c & 7) >> 1;
    const int h   = c & 1;
    const int lane4 = ((c >> 2) & 3);
    const int breg  = (c >> 4) & 1;
    const int jh = c >> 5;          // fp8 MMA index for the w half
    const int jl = 2 + (c >> 5);    // fp8 MMA index for the w_lo half
    #pragma unroll
    for (int rep = 0; rep < 2; rep++) {
        const int i = tid + rep * 512;
        const float2 v = psi[i];
        #pragma unroll
        for (int p = 0; p < 2; p++) {
            const float val = p ? v.y : v.x;
            const __nv_bfloat16 hi = __float2bfloat16(val);
            const float hif = __bfloat162float(hi);
            const int n = 2 * i + p;
            const int tile = n >> 3;
            // bf16 hi fragment
            const int idx16 = ((tile * 64 + (chunk >> 1) * 32 + (n & 7) * 4 + lq) * 4
                               + (chunk & 1) * 2 + s16) * 2 + h;
            WPH[idx16] = __bfloat16_as_ushort(hi);
            // fp8 fragments
            const unsigned char w8  = to_e4m3(val);
            const unsigned char wl8 = to_e4m3((val - hif) * 256.0f);
            const int lane = (n & 7) * 4 + lane4;
            const size_t ah = ((((size_t)tile * 64 + (size_t)(jh >> 1) * 32 + lane) * 4)
                               + (jh & 1) * 2 + breg) * 4 + (c & 3);
            const size_t al = ((((size_t)tile * 64 + (size_t)(jl >> 1) * 32 + lane) * 4)
                               + (jl & 1) * 2 + breg) * 4 + (c & 3);
            WQ8[ah] = w8;
            WQ8[al] = wl8;
        }
    }
    // zero the 8-tile padding regions
    if (c == 0) {
        if (tid < 256)
            reinterpret_cast<uint4*>(WPH + 131072)[tid] = make_uint4(0,0,0,0);
        reinterpret_cast<uint4*>(WQ8 + 256*64*16)[tid] = make_uint4(0,0,0,0);
    }
}

// ---------------------------------------------------------------------------
// MMA helpers
// ---------------------------------------------------------------------------
__device__ __forceinline__ void mma16816(float* c,
    const uint32_t* a, uint32_t b0, uint32_t b1)
{
    asm volatile(
        "mma.sync.aligned.m16n8k16.row.col.f32.bf16.bf16.f32 "
        "{%0,%1,%2,%3}, {%4,%5,%6,%7}, {%8,%9}, {%0,%1,%2,%3};"
        : "+f"(c[0]), "+f"(c[1]), "+f"(c[2]), "+f"(c[3])
        : "r"(a[0]), "r"(a[1]), "r"(a[2]), "r"(a[3]), "r"(b0), "r"(b1));
}

__device__ __forceinline__ void mma_fp8(float* c,
    const uint32_t* a, uint32_t b0, uint32_t b1)
{
    asm volatile(
        "mma.sync.aligned.m16n8k32.row.col.f32.e4m3.e4m3.f32 "
        "{%0,%1,%2,%3}, {%4,%5,%6,%7}, {%8,%9}, {%0,%1,%2,%3};"
        : "+f"(c[0]), "+f"(c[1]), "+f"(c[2]), "+f"(c[3])
        : "r"(a[0]), "r"(a[1]), "r"(a[2]), "r"(a[3]), "r"(b0), "r"(b1));
}

// ---------------------------------------------------------------------------
// Main kernel: 16 tokens/CTA, 8 warps; warp w owns tiles w + 8t (t=0..31).
// grid = 1024, 2 CTAs/SM. Per tile: 4 bf16 k16 MMAs (hi*hi) + 4 e4m3 k32 MMAs
// (merged correction y_lo*w + y_hi*w_lo, scaled by 256). Depth-1 reg prefetch.
// ---------------------------------------------------------------------------
__global__ void __launch_bounds__(256, 2) qsa_main(const float* __restrict__ x,
                                                   float* __restrict__ out)
{
    __shared__ float Y[16][64];
    __shared__ float Q[16][132];
    const int tid  = threadIdx.x;
    const int w    = tid >> 5;
    const int lane = tid & 31;
    const int m0   = blockIdx.x * 16;

    // --- load + L2-normalize 16 tokens ---
    {
        const int tk = tid >> 4;
        const int pp = tid & 15;
        const float4 f = reinterpret_cast<const float4*>(
            x + (size_t)(m0 + tk) * HID)[pp];
        float ssq = f.x*f.x + f.y*f.y + f.z*f.z + f.w*f.w;
        ssq += __shfl_xor_sync(0xffffffffu, ssq, 1);
        ssq += __shfl_xor_sync(0xffffffffu, ssq, 2);
        ssq += __shfl_xor_sync(0xffffffffu, ssq, 4);
        ssq += __shfl_xor_sync(0xffffffffu, ssq, 8);
        const float rn = rsqrtf(ssq);
        Y[tk][pp*4 + 0] = f.x * rn;
        Y[tk][pp*4 + 1] = f.y * rn;
        Y[tk][pp*4 + 2] = f.z * rn;
        Y[tk][pp*4 + 3] = f.w * rn;
    }
    __syncthreads();

    // --- bf16 A fragments (hi only): 4 k-chunks x 4 regs ---
    uint32_t Ah[4][4];
    {
        const int r0 = lane >> 2;
        const int q2 = (lane & 3) * 2;
        #pragma unroll
        for (int ch = 0; ch < 4; ch++)
            #pragma unroll
            for (int rg = 0; rg < 4; rg++) {
                const int row = r0 + 8*(rg & 1);
                const int k = ch*16 + q2 + 8*(rg >> 1);
                const __nv_bfloat16 h0 = __float2bfloat16(Y[row][k]);
                const __nv_bfloat16 h1 = __float2bfloat16(Y[row][k+1]);
                Ah[ch][rg] = ((uint32_t)__bfloat16_as_ushort(h1) << 16)
                           |  __bfloat16_as_ushort(h0);
            }
    }

    // --- fp8 A fragments: concat(y_lo*256 | y_hi), 4 MMAs x 4 regs ---
    uint32_t Af8[4][4];
    {
        const int r0 = lane >> 2;
        #pragma unroll
        for (int j = 0; j < 4; j++)
            #pragma unroll
            for (int ri = 0; ri < 4; ri++) {
                const int row = r0 + 8*(ri & 1);
                const int kbase = 32*j + 16*(ri >> 1) + (lane & 3)*4;
                uint32_t pk = 0;
                #pragma unroll
                for (int b = 0; b < 4; b++) {
                    const int kk = kbase + b;
                    float val;
                    if (kk < 64) {
                        const float yv = Y[row][kk];
                        const float yh = __bfloat162float(__float2bfloat16(yv));
                        val = (yv - yh) * 256.0f;
                    } else {
                        val = __bfloat162float(__float2bfloat16(Y[row][kk - 64]));
                    }
                    pk |= (uint32_t)to_e4m3(val) << (8*b);
                }
                Af8[j][ri] = pk;
            }
    }

    // --- main loop: 32 tiles, 8 MMAs each (4 bf16 + 4 fp8), depth-1 prefetch ---
    float q[2][4];
    #pragma unroll
    for (int r = 0; r < 2; r++)
        #pragma unroll
        for (int s = 0; s < 4; s++) q[r][s] = 0.f;

    const uint4* pH = reinterpret_cast<const uint4*>(WPH) + w*64 + lane;
    const uint4* pQ = reinterpret_cast<const uint4*>(WQ8) + w*64 + lane;

    uint4 bh0 = pH[0], bh1 = pH[32];
    uint4 q0  = pQ[0], q1  = pQ[32];

    const float inv256 = 1.0f / 256.0f;

    #pragma unroll 4
    for (int t = 0; t < 32; t++) {
        pH += 512; pQ += 512;                      // tile += 8 (padded: safe at t=31)
        const uint4 nh0 = pH[0], nh1 = pH[32];
        const uint4 nq0 = pQ[0], nq1 = pQ[32];

        float h0[4] = {0.f,0.f,0.f,0.f};
        float h1[4] = {0.f,0.f,0.f,0.f};
        float c0a[4] = {0.f,0.f,0.f,0.f};
        float c1a[4] = {0.f,0.f,0.f,0.f};
        // four independent chains of 2
        mma16816(h0,  Ah[0],  bh0.x, bh0.y);
        mma16816(h1,  Ah[1],  bh0.z, bh0.w);
        mma_fp8 (c0a, Af8[0], q0.x,  q0.y);
        mma_fp8 (c1a, Af8[1], q0.z,  q0.w);
        mma16816(h0,  Ah[2],  bh1.x, bh1.y);
        mma16816(h1,  Ah[3],  bh1.z, bh1.w);
        mma_fp8 (c0a, Af8[2], q1.x,  q1.y);
        mma_fp8 (c1a, Af8[3], q1.z,  q1.w);

        const int s = t & 3;
        const float e0 = fmaf(c0a[0] + c1a[0], inv256, h0[0] + h1[0]);
        const float e1 = fmaf(c0a[1] + c1a[1], inv256, h0[1] + h1[1]);
        const float e2 = fmaf(c0a[2] + c1a[2], inv256, h0[2] + h1[2]);
        const float e3 = fmaf(c0a[3] + c1a[3], inv256, h0[3] + h1[3]);
        q[0][s] = fmaf(e0, e0, fmaf(e1, e1, q[0][s]));
        q[1][s] = fmaf(e2, e2, fmaf(e3, e3, q[1][s]));

        bh0 = nh0; bh1 = nh1; q0 = nq0; q1 = nq1;
    }

    // --- scatter q into Q[token][j], j = 4w + 32s + (lane&3); disjoint per warp ---
    #pragma unroll
    for (int r = 0; r < 2; r++)
        #pragma unroll
        for (int s = 0; s < 4; s++) {
            const int tok = r*8 + (lane >> 2);
            const int j = 4*w + 32*s + (lane & 3);
            Q[tok][j] = q[r][s];
        }
    __syncthreads();

    // --- 128-pt WHT per token (warp w: tokens 2w, 2w+1), store out[k] = F[k+1] ---
    #pragma unroll
    for (int tt = 0; tt < 2; tt++) {
        const int tok = w*2 + tt;
        float f0 = Q[tok][lane];
        float f1 = Q[tok][lane + 32];
        float f2 = Q[tok][lane + 64];
        float f3 = Q[tok][lane + 96];
        float a0 = f0 + f1, a1 = f0 - f1, a2 = f2 + f3, a3 = f2 - f3;
        f0 = a0 + a2; f2 = a0 - a2; f1 = a1 + a3;
        #pragma unroll
        for (int e = 1; e <= 16; e <<= 1) {
            float p;
            p = __shfl_xor_sync(0xffffffffu, f0, e); f0 = (lane & e) ? (p - f0) : (f0 + p);
            p = __shfl_xor_sync(0xffffffffu, f1, e); f1 = (lane & e) ? (p - f1) : (f1 + p);
            p = __shfl_xor_sync(0xffffffffu, f2, e); f2 = (lane & e) ? (p - f2) : (f2 + p);
        }
        float* orow = out + (size_t)(m0 + tok) * HID;
        if (lane >= 1) orow[lane - 1] = f0;     // F[1..31]  -> k 0..30
        orow[lane + 31] = f1;                   // F[32..63] -> k 31..62
        if (lane == 0) orow[63] = f2;           // F[64]     -> k 63
    }
}

extern "C" void kernel_launch(void* const* d_in, const int* in_sizes, int n_in,
                              void* d_out, int out_size)
{
    const float* x   = (const float*)d_in[0];
    const float* rx0 = (const float*)d_in[1];
    const float* ry0 = (const float*)d_in[2];
    const float* ry1 = (const float*)d_in[3];
    float* out = (float*)d_out;

    const int M = in_sizes[0] / HID;   // 16384 tokens

    qsa_circuit<<<HID, 512>>>(rx0, ry0, ry1);   // W -> bf16-hi + e4m3 fragments
    qsa_main<<<M / 16, 256>>>(x, out);          // 8-MMA/tile GEMM + fold + WHT
}